// round 14
// baseline (speedup 1.0000x reference)
#include <cuda_runtime.h>

// Banded DTW (Sakoe-Chiba w=1) as a min-plus (tropical) 3x3 matrix reduction,
// single fused kernel, last-block-done.
//
// Model (R3..R13): latency/critical-path bound; 128 blocks optimal. This round:
// chunk 8->4 with 256 thr/block (halves step-loop issue time; 2 warps/SMSP),
// vec4-padded matrices through global (3 STG.128 publish, 12 LDG.128 tail).
//
// Row recurrence (costs a=|o_i-t_{i-2}|, b=|o_i-t_{i-1}|, c=|o_i-t_i|;
// a=INF at i=1, c=INF at i=n):
//   n0 = a + min(p0,p1); n1 = b + min(n0,min(p1,p2)); n2 = c + min(n1,p2)
// Min-plus linear -> ordered reduction of 3x3 tropical matrices.
// Answer = M_total[1][1].

#define NTHREADS 256
#define NBLOCKS  128
#define NWARPS   (NTHREADS / 32)      // 8
#define CHUNK    4
#define MATS_PER_LANE (NBLOCKS / 32)  // 4

__device__ float4 g_bmats[NBLOCKS * 3];  // 3 rows per matrix, w = pad
__device__ unsigned int g_ticket = 0;

__device__ __forceinline__ float finf() { return __int_as_float(0x7f800000); }

struct Mat { float m[9]; };  // row-major

__device__ __forceinline__ Mat mp_identity() {
    const float INF = finf();
    Mat M;
    M.m[0] = 0.f; M.m[1] = INF; M.m[2] = INF;
    M.m[3] = INF; M.m[4] = 0.f; M.m[5] = INF;
    M.m[6] = INF; M.m[7] = INF; M.m[8] = 0.f;
    return M;
}

// C = L o E (E earlier, L later): C[i][j] = min_k L[i][k] + E[k][j]
__device__ __forceinline__ Mat mp_combine(const Mat& L, const Mat& E) {
    Mat C;
#pragma unroll
    for (int i = 0; i < 3; ++i) {
#pragma unroll
        for (int j = 0; j < 3; ++j) {
            float v = L.m[i * 3 + 0] + E.m[0 + j];
            v = fminf(v, L.m[i * 3 + 1] + E.m[3 + j]);
            v = fminf(v, L.m[i * 3 + 2] + E.m[6 + j]);
            C.m[i * 3 + j] = v;
        }
    }
    return C;
}

// One DTW row-step applied to all three columns of M.
__device__ __forceinline__ void step_cols(Mat& M, float a, float b, float c) {
#pragma unroll
    for (int j = 0; j < 3; ++j) {
        float p0 = M.m[0 + j], p1 = M.m[3 + j], p2 = M.m[6 + j];
        float n0 = a + fminf(p0, p1);
        float n1 = b + fminf(n0, fminf(p1, p2));
        float n2 = c + fminf(n1, p2);
        M.m[0 + j] = n0; M.m[3 + j] = n1; M.m[6 + j] = n2;
    }
}

// Order-preserving in-warp tree over LEVELS shuffle stages.
// Lane t holds segment t (ascending = later). Result lands in lane 0.
template <int LEVELS>
__device__ __forceinline__ void warp_reduce_mat(Mat& M, int lane) {
#pragma unroll
    for (int s = 1; s < (1 << LEVELS); s <<= 1) {
        Mat other;
#pragma unroll
        for (int q = 0; q < 9; ++q)
            other.m[q] = __shfl_down_sync(0xffffffffu, M.m[q], s);
        if ((lane & (2 * s - 1)) == 0) M = mp_combine(other, M);
    }
}

__device__ __forceinline__ Mat load_bmat(int idx) {
    Mat M;
    float4 r0 = __ldcg(&g_bmats[idx * 3 + 0]);
    float4 r1 = __ldcg(&g_bmats[idx * 3 + 1]);
    float4 r2 = __ldcg(&g_bmats[idx * 3 + 2]);
    M.m[0] = r0.x; M.m[1] = r0.y; M.m[2] = r0.z;
    M.m[3] = r1.x; M.m[4] = r1.y; M.m[5] = r1.z;
    M.m[6] = r2.x; M.m[7] = r2.y; M.m[8] = r2.z;
    return M;
}

__global__ void __launch_bounds__(NTHREADS) dtw_fused(
    const float* __restrict__ oseq, const float* __restrict__ tgt,
    int n, int chunk, float* __restrict__ out) {
    const float INF = finf();
    const int tid = threadIdx.x;
    const int lane = tid & 31;
    const int warp = tid >> 5;
    const int gid = blockIdx.x * NTHREADS + tid;
    const int s0 = gid * chunk;  // first step handled is i = s0 + 1 (1-based)

    Mat M;

    // Block-uniform fast-path predicate so warp shuffles below are full-warp.
    const bool fast = (chunk == CHUNK) &&
                      ((blockIdx.x * NTHREADS + NTHREADS) * CHUNK <= n);

    if (fast) {
        // One float4 per array; neighbor scalars via warp shuffle.
        float4 o0 = *(const float4*)(oseq + s0);
        float4 t0 = *(const float4*)(tgt + s0);

        // t[s0-1]: previous lane's t0.w ; t[s0+4]: next lane's t0.x
        float tm1 = __shfl_up_sync(0xffffffffu, t0.w, 1);
        if (lane == 0) tm1 = (s0 >= 1) ? __ldg(tgt + s0 - 1) : 0.f;
        float tp4 = __shfl_down_sync(0xffffffffu, t0.x, 1);
        if (lane == 31) tp4 = (s0 + 4 < n) ? __ldg(tgt + s0 + 4) : 0.f;

        float o[4] = {o0.x, o0.y, o0.z, o0.w};
        float t[6] = {tm1, t0.x, t0.y, t0.z, t0.w, tp4};

        // Step 0 specialized: single-step matrix from identity is closed-form
        //   [[a, a, INF], [a+b, b, b], [a+b+c, b+c, c]]
        {
            float a = (s0 >= 1) ? fabsf(o[0] - t[0]) : INF;   // i=s0+1 >= 2
            float b =             fabsf(o[0] - t[1]);
            float c =             fabsf(o[0] - t[2]);         // i=s0+1 <= n-1 always (s0+1 < n)
            float ab = a + b;
            M.m[0] = a;      M.m[1] = a;     M.m[2] = INF;
            M.m[3] = ab;     M.m[4] = b;     M.m[5] = b;
            M.m[6] = ab + c; M.m[7] = b + c; M.m[8] = c;
        }
#pragma unroll
        for (int k = 1; k < CHUNK; ++k) {
            const int i = s0 + 1 + k;
            float a =                fabsf(o[k] - t[k]);       // i >= 2 always here
            float b =                fabsf(o[k] - t[k + 1]);
            float c = (i <= n - 1) ? fabsf(o[k] - t[k + 2]) : INF;
            step_cols(M, a, b, c);
        }
    } else {
        // generic guarded path
        M = mp_identity();
        for (int k = 0; k < chunk; ++k) {
            const int i = s0 + 1 + k;
            if (i > n) break;
            float o = __ldg(oseq + (i - 1));
            float a = (i >= 2)     ? fabsf(o - __ldg(tgt + (i - 2))) : INF;
            float b =                fabsf(o - __ldg(tgt + (i - 1)));
            float c = (i <= n - 1) ? fabsf(o - __ldg(tgt + i))       : INF;
            step_cols(M, a, b, c);
        }
    }

    // In-warp ordered reduce: lane 0 of each warp holds its warp product.
    warp_reduce_mat<5>(M, lane);

    __shared__ Mat swarp[NWARPS];
    if (lane == 0) swarp[warp] = M;
    __syncthreads();

    // Warp 0 finishes the block (lanes 0..7 lane-parallel, 3 shuffle levels),
    // publishes as 3 vec4 rows, takes a ticket; last block reduces all 128.
    if (warp == 0) {
        Mat B = (lane < NWARPS) ? swarp[lane] : mp_identity();
        warp_reduce_mat<3>(B, lane);  // 8 warps -> 3 levels

        unsigned int tk = 0;
        if (lane == 0) {
            const int bi = blockIdx.x * 3;
            __stcg(&g_bmats[bi + 0], make_float4(B.m[0], B.m[1], B.m[2], 0.f));
            __stcg(&g_bmats[bi + 1], make_float4(B.m[3], B.m[4], B.m[5], 0.f));
            __stcg(&g_bmats[bi + 2], make_float4(B.m[6], B.m[7], B.m[8], 0.f));
            __threadfence();
            tk = atomicAdd(&g_ticket, 1u);
        }
        tk = __shfl_sync(0xffffffffu, tk, 0);

        if (tk == NBLOCKS - 1) {
            __threadfence();  // acquire: see all blocks' g_bmats
            // Lane-parallel tail: lane folds block-mats [4l .. 4l+3]
            // (index ascending = later), then 5-level ordered tree.
            const int base = lane * MATS_PER_LANE;
            Mat F = load_bmat(base);
#pragma unroll
            for (int r = 1; r < MATS_PER_LANE; ++r)
                F = mp_combine(load_bmat(base + r), F);  // later o earlier
            warp_reduce_mat<5>(F, lane);
            if (lane == 0) {
                // v_init = (INF, 0, INF); answer = M_total[1][1]
                out[0] = F.m[4];
                g_ticket = 0;  // reset for next graph replay
            }
        }
    }
}

extern "C" void kernel_launch(void* const* d_in, const int* in_sizes, int n_in,
                              void* d_out, int out_size) {
    const float* oseq = (const float*)d_in[0];
    const float* tgt  = (const float*)d_in[1];
    const int n = in_sizes[0];

    const int P = NTHREADS * NBLOCKS;
    const int chunk = (n + P - 1) / P;

    dtw_fused<<<NBLOCKS, NTHREADS>>>(oseq, tgt, n, chunk, (float*)d_out);
}